// round 12
// baseline (speedup 1.0000x reference)
#include <cuda_runtime.h>
#include <cuda_bf16.h>
#include <cstdint>

// Retrace: per-(b,d) reverse affine scan + MSE reduction.
// Shapes: B=2048, T=512, D=16. fp32. Output: 1 fp32 scalar.
// R11: R9 structure (512 thr, 16 segments x 32 steps, 32 chains/block,
// grid 1024) but global loads staged via cp.async double-buffered into
// per-thread smem slots -> loads in flight no longer consume registers.

#define RB 2048
#define RT 512
#define RD 16
#define NSEG 16
#define SEGLEN 32
#define CHAINS_PER_BLK 32
#define NCHUNK 8                 // 8 chunks x 4 steps = 32 steps
#define VPS 6                    // values per step
#define CHUNK_FLOATS (4 * VPS)   // 24
#define BLK 512
#define GAMMA 0.99f

__device__ __forceinline__ void cpa4(float* s, const float* g) {
    uint32_t sa = (uint32_t)__cvta_generic_to_shared(s);
    asm volatile("cp.async.ca.shared.global [%0], [%1], 4;" :: "r"(sa), "l"(g));
}

__global__ __launch_bounds__(BLK, 2)
void retrace_cp_kernel(const float* __restrict__ Q,
                       const float* __restrict__ eQ,
                       const float* __restrict__ tQ,
                       const float* __restrict__ rw,
                       const float* __restrict__ tpp,
                       const float* __restrict__ bpp,
                       float* __restrict__ out)
{
    extern __shared__ float buf[];           // [2][CHUNK_FLOATS][BLK] = 96 KB
    const int tid  = threadIdx.x;
    const int lane = tid & 31;               // chain within block
    const int seg  = tid >> 5;               // segment 0..15
    const int chain = blockIdx.x * CHAINS_PER_BLK + lane;
    const int b = chain >> 4;                // D = 16
    const int d = chain & 15;

    const size_t base = (size_t)b * (RT * RD) + d;
    const float* q_p   = Q   + base;
    const float* e_p   = eQ  + base;
    const float* tq_p  = tQ  + base;
    const float* r_p   = rw  + base;
    const float* tpp_p = tpp + base;
    const float* bpp_p = bpp + (size_t)b * RT;

    const int lo = seg * SEGLEN;
    const int hi = (seg == NSEG - 1) ? (RT - 2) : (lo + SEGLEN - 1);

    // slot address helper: buf[(p*CHUNK_FLOATS + i)*BLK + tid]
#define SLOT(p, i) (buf + ((p) * CHUNK_FLOATS + (i)) * BLK + tid)

    // issue one 4-step chunk c into buffer parity p
#define ISSUE(c, p)                                                        \
    {                                                                      \
        _Pragma("unroll")                                                  \
        for (int k = 0; k < 4; ++k) {                                      \
            const int t = hi - (c) * 4 - k;                                \
            const int j = t + 1;                                           \
            cpa4(SLOT(p, k * VPS + 0), tpp_p + (size_t)j * RD);            \
            cpa4(SLOT(p, k * VPS + 1), bpp_p + j);                         \
            cpa4(SLOT(p, k * VPS + 2), e_p   + (size_t)j * RD);            \
            cpa4(SLOT(p, k * VPS + 3), tq_p  + (size_t)j * RD);            \
            cpa4(SLOT(p, k * VPS + 4), r_p   + (size_t)t * RD);            \
            cpa4(SLOT(p, k * VPS + 5), q_p   + (size_t)t * RD);            \
        }                                                                  \
        asm volatile("cp.async.commit_group;" ::: "memory");               \
    }

    float P = 1.0f, S = 0.0f;
    float sumD2 = 0.0f, sumDP = 0.0f, sumP2 = 0.0f;

    ISSUE(0, 0);
    ISSUE(1, 1);

    #pragma unroll
    for (int c = 0; c < NCHUNK; ++c) {
        if (c < NCHUNK - 1) {
            asm volatile("cp.async.wait_group 1;" ::: "memory");
        } else {
            asm volatile("cp.async.wait_group 0;" ::: "memory");
        }
        const int p = c & 1;
        #pragma unroll
        for (int k = 0; k < 4; ++k) {
            const int t = hi - c * 4 - k;
            if (t >= lo) {                    // only seg 15's last chunk skips
                float lt = *SLOT(p, k * VPS + 0);
                float lb = *SLOT(p, k * VPS + 1);
                float le = *SLOT(p, k * VPS + 2);
                float lq = *SLOT(p, k * VPS + 3);
                float lr = *SLOT(p, k * VPS + 4);
                float lQ = *SLOT(p, k * VPS + 5);

                float gc  = GAMMA * __expf(fminf(lt - lb, 0.0f));
                float bse = fmaf(GAMMA, le, lr);
                bse       = fmaf(-gc, lq, bse);
                P = gc * P;
                S = fmaf(gc, S, bse);
                float dv = lQ - S;            // diff = dv - P*x
                sumD2 = fmaf(dv, dv, sumD2);
                sumDP = fmaf(dv, P,  sumDP);
                sumP2 = fmaf(P,  P,  sumP2);
            }
        }
        if (c + 2 < NCHUNK) ISSUE(c + 2, p);
    }

    __shared__ float shA [NSEG][CHAINS_PER_BLK];
    __shared__ float shB [NSEG][CHAINS_PER_BLK];
    __shared__ float shD2[NSEG][CHAINS_PER_BLK];
    __shared__ float shDP[NSEG][CHAINS_PER_BLK];
    __shared__ float shP2[NSEG][CHAINS_PER_BLK];
    shA [seg][lane] = P;
    shB [seg][lane] = S;
    shD2[seg][lane] = sumD2;
    shDP[seg][lane] = sumDP;
    shP2[seg][lane] = sumP2;
    __syncthreads();

    // Warp 0: serial combine over 16 segments for each of the 32 chains.
    if (seg == 0) {
        float x = tq_p[(size_t)(RT - 1) * RD];   // initial carry = target_Q[:, -1]
        float acc = 0.0f;
        #pragma unroll
        for (int s = NSEG - 1; s >= 0; --s) {
            float a2 = shD2[s][lane], dp = shDP[s][lane], p2 = shP2[s][lane];
            acc += fmaf(x, fmaf(x, p2, -2.0f * dp), a2);
            x = fmaf(shA[s][lane], x, shB[s][lane]);
        }
        const float inv_n = 1.0f / (float)((size_t)RB * (RT - 1) * RD);
        acc *= inv_n;

        #pragma unroll
        for (int off = 16; off > 0; off >>= 1)
            acc += __shfl_down_sync(0xFFFFFFFFu, acc, off);
        if (lane == 0)
            atomicAdd(out, acc);
    }
}

extern "C" void kernel_launch(void* const* d_in, const int* in_sizes, int n_in,
                              void* d_out, int out_size)
{
    const float* Q   = (const float*)d_in[0];
    const float* eQ  = (const float*)d_in[1];
    const float* tQ  = (const float*)d_in[2];
    const float* rw  = (const float*)d_in[3];
    const float* tpp = (const float*)d_in[4];
    const float* bpp = (const float*)d_in[5];
    float* out = (float*)d_out;

    const int dyn_smem = 2 * CHUNK_FLOATS * BLK * sizeof(float);   // 98304
    static bool attr_set = false;
    if (!attr_set) {
        cudaFuncSetAttribute(retrace_cp_kernel,
                             cudaFuncAttributeMaxDynamicSharedMemorySize, dyn_smem);
        attr_set = true;
    }

    cudaMemsetAsync(out, 0, sizeof(float), 0);

    const int blocks = (RB * RD) / CHAINS_PER_BLK;   // 1024
    retrace_cp_kernel<<<blocks, BLK, dyn_smem>>>(Q, eQ, tQ, rw, tpp, bpp, out);
}

// round 13
// speedup vs baseline: 1.8971x; 1.8971x over previous
#include <cuda_runtime.h>
#include <cuda_bf16.h>

// Retrace: per-(b,d) reverse affine scan + MSE reduction.
// Shapes: B=2048, T=512, D=16. All inputs fp32. Output: 1 fp32 scalar.
// Segment-parallel: q_t = gc_t * q_{t+1} + base_t is affine in the carry ->
// each segment yields (P, S) with q = P*x + S; squared error is quadratic in
// the carry-in x: sumD2 - 2x*sumDP + x^2*sumP2.
// R12: R9 inner loop unchanged; block 512 -> 384 (NSEG=12). 56 regs x 384 thr
// x 3 blocks = 64512 regs/SM -> 36 resident warps vs 32 at 512-thr blocks.

#define RB 2048
#define RT 512
#define RD 16
#define NSEG 12
#define SEGLEN 43            // segs 0..10: 43 steps; seg 11: t=473..510 (38)
#define CHAINS_PER_BLK 32
#define GAMMA 0.99f

__global__ __launch_bounds__(384, 3)
void retrace_seg_kernel(const float* __restrict__ Q,
                        const float* __restrict__ eQ,
                        const float* __restrict__ tQ,
                        const float* __restrict__ rw,
                        const float* __restrict__ tpp,
                        const float* __restrict__ bpp,
                        float* __restrict__ out)
{
    const int lane = threadIdx.x & 31;       // chain within block
    const int seg  = threadIdx.x >> 5;       // time segment 0..11
    const int chain = blockIdx.x * CHAINS_PER_BLK + lane;  // 0 .. B*D-1
    const int b = chain >> 4;                // D = 16
    const int d = chain & 15;

    const size_t base = (size_t)b * (RT * RD) + d;
    const float* q_p   = Q   + base;
    const float* e_p   = eQ  + base;
    const float* tq_p  = tQ  + base;
    const float* r_p   = rw  + base;
    const float* tpp_p = tpp + base;
    const float* bpp_p = bpp + (size_t)b * RT;

    const int lo = seg * SEGLEN;
    int hi = lo + SEGLEN - 1;
    if (hi > RT - 2) hi = RT - 2;            // clamp for last segment

    // Backward scan within segment: q = P*x + S (x = carry entering at t=hi+1)
    float P = 1.0f, S = 0.0f;
    float sumD2 = 0.0f, sumDP = 0.0f, sumP2 = 0.0f;

    #pragma unroll 4
    for (int t = hi; t >= lo; --t) {
        const int j = t + 1;
        float lw  = tpp_p[j * RD] - bpp_p[j];
        float gc  = GAMMA * __expf(fminf(lw, 0.0f));
        float bse = fmaf(GAMMA, e_p[j * RD], r_p[t * RD]);
        bse       = fmaf(-gc, tq_p[j * RD], bse);
        P = gc * P;
        S = fmaf(gc, S, bse);
        float dv = q_p[t * RD] - S;          // diff = dv - P*x
        sumD2 = fmaf(dv, dv, sumD2);
        sumDP = fmaf(dv, P,  sumDP);
        sumP2 = fmaf(P,  P,  sumP2);
    }

    __shared__ float shA [NSEG][CHAINS_PER_BLK];
    __shared__ float shB [NSEG][CHAINS_PER_BLK];
    __shared__ float shD2[NSEG][CHAINS_PER_BLK];
    __shared__ float shDP[NSEG][CHAINS_PER_BLK];
    __shared__ float shP2[NSEG][CHAINS_PER_BLK];
    shA [seg][lane] = P;
    shB [seg][lane] = S;
    shD2[seg][lane] = sumD2;
    shDP[seg][lane] = sumDP;
    shP2[seg][lane] = sumP2;
    __syncthreads();

    // Warp 0: serial combine over 12 segments for each of the 32 chains.
    if (seg == 0) {
        float x = tq_p[(size_t)(RT - 1) * RD];   // initial carry = target_Q[:, -1]
        float acc = 0.0f;
        #pragma unroll
        for (int s = NSEG - 1; s >= 0; --s) {
            float a2 = shD2[s][lane], dp = shDP[s][lane], p2 = shP2[s][lane];
            acc += fmaf(x, fmaf(x, p2, -2.0f * dp), a2);
            x = fmaf(shA[s][lane], x, shB[s][lane]);
        }
        const float inv_n = 1.0f / (float)((size_t)RB * (RT - 1) * RD);
        acc *= inv_n;

        #pragma unroll
        for (int off = 16; off > 0; off >>= 1)
            acc += __shfl_down_sync(0xFFFFFFFFu, acc, off);
        if (lane == 0)
            atomicAdd(out, acc);
    }
}

extern "C" void kernel_launch(void* const* d_in, const int* in_sizes, int n_in,
                              void* d_out, int out_size)
{
    const float* Q   = (const float*)d_in[0];
    const float* eQ  = (const float*)d_in[1];
    const float* tQ  = (const float*)d_in[2];
    const float* rw  = (const float*)d_in[3];
    const float* tpp = (const float*)d_in[4];
    const float* bpp = (const float*)d_in[5];
    float* out = (float*)d_out;

    cudaMemsetAsync(out, 0, sizeof(float), 0);

    const int blocks = (RB * RD) / CHAINS_PER_BLK;   // 1024
    retrace_seg_kernel<<<blocks, NSEG * 32>>>(Q, eQ, tQ, rw, tpp, bpp, out);
}